// round 3
// baseline (speedup 1.0000x reference)
#include <cuda_runtime.h>
#include <cstdint>
#include <cstdio>

#define B_ROWS  131072
#define IN_DIM  1024
#define H_DIM   256
#define OUT_DIM 256
#define M_TILE  64
#define THREADS 256
#define LDX 36      // xs row stride (words): 36 % 32 = 4 -> conflict-free A frags
#define LDW 264     // ws row stride (words): 264 % 32 = 8 -> conflict-free B frags
#define LDH 264     // hs row stride

#define SMEM_BYTES ((M_TILE*LDX + 32*LDW + M_TILE*LDH) * 4)  // 110592

__device__ __forceinline__ unsigned f2tf(float f) {
    unsigned u;
    asm("cvt.rna.tf32.f32 %0, %1;" : "=r"(u) : "f"(f));
    return u;
}

__device__ __forceinline__ void mma8(float* c,
                                     unsigned a0, unsigned a1, unsigned a2, unsigned a3,
                                     unsigned b0, unsigned b1) {
    asm volatile(
        "mma.sync.aligned.m16n8k8.row.col.f32.tf32.tf32.f32 "
        "{%0,%1,%2,%3}, {%4,%5,%6,%7}, {%8,%9}, {%0,%1,%2,%3};"
        : "+f"(c[0]), "+f"(c[1]), "+f"(c[2]), "+f"(c[3])
        : "r"(a0), "r"(a1), "r"(a2), "r"(a3), "r"(b0), "r"(b1));
}

__device__ __forceinline__ float apply_act(float z, int id) {
    if (id == 0) return fmaxf(z, 0.0f);
    if (id == 1) return tanhf(z);
    if (id == 2) return 0.5f * z * (1.0f + erff(z * 0.7071067811865475f));
    return 1.0f / (1.0f + __expf(-z));
}

extern __shared__ unsigned char smem_raw[];

__global__ void __launch_bounds__(THREADS, 2) het_mlp_kernel(
    const float* __restrict__ x,    const float* __restrict__ W1,  const float* __restrict__ b1,
    const float* __restrict__ W2,   const float* __restrict__ b2,
    const float* __restrict__ Wout, const float* __restrict__ bout,
    const int* __restrict__ act1,   const int* __restrict__ act2,
    float* __restrict__ out)
{
    unsigned* xs = (unsigned*)smem_raw;        // [64][36]  tf32 bits
    unsigned* ws = xs + M_TILE * LDX;          // [32][264] tf32 bits
    unsigned* hs = ws + 32 * LDW;              // [64][264] tf32 bits

    const int t    = threadIdx.x;
    const int lane = t & 31;
    const int wid  = t >> 5;
    const int wm   = wid & 3;     // warp row group (4 warps along M)
    const int wn   = wid >> 2;    // warp col group (2 warps along N)
    const int g    = lane >> 2;   // 0..7
    const int tg   = lane & 3;    // 0..3
    const int row0 = blockIdx.x * M_TILE;
    const int arow = wm * 16;
    const int wcol = wn * 128;

    float c[16][4];
    #pragma unroll
    for (int j = 0; j < 16; j++) { c[j][0] = c[j][1] = c[j][2] = c[j][3] = 0.0f; }

    // ================= Layer 1: h1 = act1(x @ W1 + b1) =================
    for (int kc = 0; kc < IN_DIM / 32; kc++) {
        __syncthreads();
        // fill x tile [64][32]
        {
            const float* xp = x + (size_t)row0 * IN_DIM + kc * 32;
            #pragma unroll
            for (int i = 0; i < 2; i++) {
                int idx = t + i * THREADS;           // 0..511
                int r = idx >> 3, k4 = idx & 7;
                float4 v = *(const float4*)(xp + (size_t)r * IN_DIM + k4 * 4);
                unsigned* d = xs + r * LDX + k4 * 4;
                d[0] = f2tf(v.x); d[1] = f2tf(v.y); d[2] = f2tf(v.z); d[3] = f2tf(v.w);
            }
        }
        // fill W1 chunk [32][256]
        {
            const float4* wp = (const float4*)(W1 + (size_t)kc * 32 * H_DIM);
            #pragma unroll
            for (int i = 0; i < 8; i++) {
                int idx = t + i * THREADS;           // 0..2047
                float4 v = wp[idx];
                int k = idx >> 6, n4 = idx & 63;
                unsigned* d = ws + k * LDW + n4 * 4;
                d[0] = f2tf(v.x); d[1] = f2tf(v.y); d[2] = f2tf(v.z); d[3] = f2tf(v.w);
            }
        }
        __syncthreads();
        #pragma unroll
        for (int ks = 0; ks < 4; ks++) {
            int k0 = ks * 8;
            unsigned a0 = xs[(arow + g)     * LDX + k0 + tg];
            unsigned a1 = xs[(arow + g + 8) * LDX + k0 + tg];
            unsigned a2 = xs[(arow + g)     * LDX + k0 + tg + 4];
            unsigned a3 = xs[(arow + g + 8) * LDX + k0 + tg + 4];
            const unsigned* w0 = ws + (k0 + tg)     * LDW + wcol + g;
            const unsigned* w1 = ws + (k0 + tg + 4) * LDW + wcol + g;
            #pragma unroll
            for (int j = 0; j < 16; j++)
                mma8(c[j], a0, a1, a2, a3, w0[j * 8], w1[j * 8]);
        }
    }
    // epilogue 1 -> hs (bias + per-column act, stored as tf32)
    #pragma unroll
    for (int j = 0; j < 16; j++) {
        int col = wcol + j * 8 + 2 * tg;
        int   id0 = __ldg(act1 + col), id1 = __ldg(act1 + col + 1);
        float bb0 = __ldg(b1 + col),   bb1 = __ldg(b1 + col + 1);
        #pragma unroll
        for (int h = 0; h < 2; h++) {
            int row = arow + g + 8 * h;
            float z0 = c[j][2 * h]     + bb0;
            float z1 = c[j][2 * h + 1] + bb1;
            hs[row * LDH + col]     = f2tf(apply_act(z0, id0));
            hs[row * LDH + col + 1] = f2tf(apply_act(z1, id1));
        }
    }

    // ================= Layer 2: h2 = act2(h1 @ W2 + b2) =================
    #pragma unroll
    for (int j = 0; j < 16; j++) { c[j][0] = c[j][1] = c[j][2] = c[j][3] = 0.0f; }
    for (int kc = 0; kc < H_DIM / 32; kc++) {
        __syncthreads();   // covers hs writes (iter 0) and ws reuse
        {
            const float4* wp = (const float4*)(W2 + (size_t)kc * 32 * H_DIM);
            #pragma unroll
            for (int i = 0; i < 8; i++) {
                int idx = t + i * THREADS;
                float4 v = wp[idx];
                int k = idx >> 6, n4 = idx & 63;
                unsigned* d = ws + k * LDW + n4 * 4;
                d[0] = f2tf(v.x); d[1] = f2tf(v.y); d[2] = f2tf(v.z); d[3] = f2tf(v.w);
            }
        }
        __syncthreads();
        #pragma unroll
        for (int ks = 0; ks < 4; ks++) {
            int k0 = kc * 32 + ks * 8;
            unsigned a0 = hs[(arow + g)     * LDH + k0 + tg];
            unsigned a1 = hs[(arow + g + 8) * LDH + k0 + tg];
            unsigned a2 = hs[(arow + g)     * LDH + k0 + tg + 4];
            unsigned a3 = hs[(arow + g + 8) * LDH + k0 + tg + 4];
            const unsigned* w0 = ws + ((k0 & 31) + tg)     * LDW + wcol + g;
            const unsigned* w1 = ws + ((k0 & 31) + tg + 4) * LDW + wcol + g;
            #pragma unroll
            for (int j = 0; j < 16; j++)
                mma8(c[j], a0, a1, a2, a3, w0[j * 8], w1[j * 8]);
        }
    }
    __syncthreads();  // all warps done reading hs before overwrite
    #pragma unroll
    for (int j = 0; j < 16; j++) {
        int col = wcol + j * 8 + 2 * tg;
        int   id0 = __ldg(act2 + col), id1 = __ldg(act2 + col + 1);
        float bb0 = __ldg(b2 + col),   bb1 = __ldg(b2 + col + 1);
        #pragma unroll
        for (int h = 0; h < 2; h++) {
            int row = arow + g + 8 * h;
            float z0 = c[j][2 * h]     + bb0;
            float z1 = c[j][2 * h + 1] + bb1;
            hs[row * LDH + col]     = f2tf(apply_act(z0, id0));
            hs[row * LDH + col + 1] = f2tf(apply_act(z1, id1));
        }
    }

    // ================= Layer 3: out = h2 @ Wout + bout =================
    #pragma unroll
    for (int j = 0; j < 16; j++) { c[j][0] = c[j][1] = c[j][2] = c[j][3] = 0.0f; }
    for (int kc = 0; kc < H_DIM / 32; kc++) {
        __syncthreads();
        {
            const float4* wp = (const float4*)(Wout + (size_t)kc * 32 * H_DIM);
            #pragma unroll
            for (int i = 0; i < 8; i++) {
                int idx = t + i * THREADS;
                float4 v = wp[idx];
                int k = idx >> 6, n4 = idx & 63;
                unsigned* d = ws + k * LDW + n4 * 4;
                d[0] = f2tf(v.x); d[1] = f2tf(v.y); d[2] = f2tf(v.z); d[3] = f2tf(v.w);
            }
        }
        __syncthreads();
        #pragma unroll
        for (int ks = 0; ks < 4; ks++) {
            int k0 = kc * 32 + ks * 8;
            unsigned a0 = hs[(arow + g)     * LDH + k0 + tg];
            unsigned a1 = hs[(arow + g + 8) * LDH + k0 + tg];
            unsigned a2 = hs[(arow + g)     * LDH + k0 + tg + 4];
            unsigned a3 = hs[(arow + g + 8) * LDH + k0 + tg + 4];
            const unsigned* w0 = ws + ((k0 & 31) + tg)     * LDW + wcol + g;
            const unsigned* w1 = ws + ((k0 & 31) + tg + 4) * LDW + wcol + g;
            #pragma unroll
            for (int j = 0; j < 16; j++)
                mma8(c[j], a0, a1, a2, a3, w0[j * 8], w1[j * 8]);
        }
    }
    // epilogue 3 -> gmem
    #pragma unroll
    for (int j = 0; j < 16; j++) {
        int col = wcol + j * 8 + 2 * tg;
        float bb0 = __ldg(bout + col), bb1 = __ldg(bout + col + 1);
        #pragma unroll
        for (int h = 0; h < 2; h++) {
            int row = row0 + arow + g + 8 * h;
            float2 v = make_float2(c[j][2 * h] + bb0, c[j][2 * h + 1] + bb1);
            *(float2*)(out + (size_t)row * OUT_DIM + col) = v;
        }
    }
}

extern "C" void kernel_launch(void* const* d_in, const int* in_sizes, int n_in,
                              void* d_out, int out_size) {
    (void)in_sizes; (void)n_in; (void)out_size;
    cudaFuncSetAttribute(het_mlp_kernel,
                         cudaFuncAttributeMaxDynamicSharedMemorySize, SMEM_BYTES);
    dim3 grid(B_ROWS / M_TILE);
    het_mlp_kernel<<<grid, THREADS, SMEM_BYTES>>>(
        (const float*)d_in[0], (const float*)d_in[1], (const float*)d_in[2],
        (const float*)d_in[3], (const float*)d_in[4], (const float*)d_in[5],
        (const float*)d_in[6], (const int*)d_in[7], (const int*)d_in[8],
        (float*)d_out);
}